// round 11
// baseline (speedup 1.0000x reference)
#include <cuda_runtime.h>
#include <cuda_fp16.h>
#include <cstdint>

#define TT 4096   // tokens = B*S
#define HH 1024   // hidden
#define FF 4096   // ffn
#define NE 8      // experts

#define BM 128
#define BN 64
#define BK 32
#define ASTAGES 4                   // A: cp.async pipeline depth
#define TILES_M (TT / BM)           // 32 per expert (worst case)
#define A_STAGE_BYTES 8192          // 128 x 32 fp16
#define B_STAGE_BYTES 4096          // 16 pair-rows x 64 half2 (256B rows)
#define SMEM_BYTES (ASTAGES * A_STAGE_BYTES + 2 * B_STAGE_BYTES + 256)

// ---------------- scratch (static device globals; no runtime alloc) --------
__device__ __half g_xg [(size_t)(TT + BM) * HH];  // gathered acts, fp16
__device__ __half g_mid[(size_t)(TT + BM) * FF];  // fc1 out (perm order), fp16
__device__ int    g_perm[TT];
__device__ int    g_expert_of[TT];
__device__ float  g_maxprob[TT];
__device__ int    g_cnt[NE];        // zero at load; scan re-zeroes each run
__device__ int    g_off[NE + 1];
__device__ int    g_cur[NE];

// ---------------- helpers ---------------------------------------------------
__device__ __forceinline__ uint32_t smem_u32(const void* p) {
    uint32_t a;
    asm("{ .reg .u64 t; cvta.to.shared.u64 t, %1; cvt.u32.u64 %0, t; }" : "=r"(a) : "l"(p));
    return a;
}
// pack two f32 -> f16x2 (first src -> HIGH half, second -> LOW half)
__device__ __forceinline__ uint32_t pack_f16x2(float hi, float lo) {
    uint32_t d;
    asm("cvt.rn.f16x2.f32 %0, %1, %2;" : "=r"(d) : "f"(hi), "f"(lo));
    return d;
}
__device__ __forceinline__ float gelu_exact(float v) {
    return 0.5f * v * (1.0f + erff(v * 0.7071067811865476f));
}
__device__ __forceinline__ void cp_async16(uint32_t dst, const void* src) {
    asm volatile("cp.async.cg.shared.global [%0], [%1], 16;" :: "r"(dst), "l"(src));
}
__device__ __forceinline__ void cp_commit() {
    asm volatile("cp.async.commit_group;" ::: "memory");
}
template<int N>
__device__ __forceinline__ void cp_wait() {
    asm volatile("cp.async.wait_group %0;" :: "n"(N) : "memory");
}

// ---------------- routing kernels ------------------------------------------
__global__ void router_kernel(const float* __restrict__ x,
                              const float* __restrict__ Wr,
                              const float* __restrict__ br) {
    int warp = (blockIdx.x * blockDim.x + threadIdx.x) >> 5;
    int lane = threadIdx.x & 31;
    if (warp >= TT) return;
    const float* xr = x + (size_t)warp * HH;
    float acc[NE];
#pragma unroll
    for (int e = 0; e < NE; e++) acc[e] = 0.f;
    for (int i = lane; i < HH; i += 32) {
        float xv = xr[i];
        const float4* w4 = reinterpret_cast<const float4*>(Wr + i * NE);
        float4 w0 = w4[0], w1 = w4[1];
        acc[0] += xv * w0.x; acc[1] += xv * w0.y;
        acc[2] += xv * w0.z; acc[3] += xv * w0.w;
        acc[4] += xv * w1.x; acc[5] += xv * w1.y;
        acc[6] += xv * w1.z; acc[7] += xv * w1.w;
    }
#pragma unroll
    for (int e = 0; e < NE; e++) {
#pragma unroll
        for (int o = 16; o > 0; o >>= 1)
            acc[e] += __shfl_xor_sync(0xffffffffu, acc[e], o);
    }
    if (lane == 0) {
        float best = acc[0] + br[0]; int bi = 0;
#pragma unroll
        for (int e = 1; e < NE; e++) {
            float v = acc[e] + br[e];
            if (v > best) { best = v; bi = e; }
        }
        g_expert_of[warp] = bi;
        g_maxprob[warp]   = 1.0f / (1.0f + expf(-best));
        atomicAdd(&g_cnt[bi], 1);
    }
}

// offsets; self-resets g_cnt so no separate init launch is needed
__global__ void scan_kernel() {
    if (threadIdx.x == 0) {
        int off = 0;
        for (int e = 0; e < NE; e++) {
            g_off[e] = off; g_cur[e] = off; off += g_cnt[e];
            g_cnt[e] = 0;                    // ready for next invocation
        }
        g_off[NE] = off;
    }
}

// fused: compute perm slot for this token AND gather its row to fp16
__global__ void permgather_kernel(const float* __restrict__ x) {
    __shared__ int s_slot;
    int tok = blockIdx.x;
    if (threadIdx.x == 0) {
        int e = g_expert_of[tok];
        int slot = atomicAdd(&g_cur[e], 1);
        g_perm[slot] = tok;
        s_slot = slot;
    }
    __syncthreads();
    int slot = s_slot;
    const float4* src = reinterpret_cast<const float4*>(x + (size_t)tok * HH);
    int c = threadIdx.x;            // 256 threads, 4 elems each
    float4 v = src[c];
    __half2 h0 = __floats2half2_rn(v.x, v.y);
    __half2 h1 = __floats2half2_rn(v.z, v.w);
    uint2 pk;
    pk.x = *reinterpret_cast<uint32_t*>(&h0);
    pk.y = *reinterpret_cast<uint32_t*>(&h1);
    *reinterpret_cast<uint2*>(g_xg + (size_t)slot * HH + 4 * c) = pk;
}

// ---------------- pipelined fp16 grouped GEMM (BM=128 x BN=64) --------------
// FC1: g_mid = fp16( gelu( g_xg @ W1[e] ) )   K=HH, N over FF
// FC2: out   = ( g_mid @ W2[e] ) * p          K=FF, N over HH
//
// 256 threads, 8 warps (4 m x 2 n), warp tile 32x32, mma m16n8k16 f16.f16.f32.
// 3 CTAs/SM (24 warps) for latency hiding — the R10 profile showed
// tensor=32.6%, occ=22.8%: latency-bound, not pipe-bound.
// Smem A: fp16 [128][32], 64B rows, chunk16 ^ ((m>>1)&3), 4-stage cp.async.
// Smem B: half2-packed [16 pair-rows][64 n], 256B rows,
//         chunk16 ^ ((pr&3)<<1), double-buffered manual LDG->cvt->STS.
template<int KTOT, bool FC2>
__global__ __launch_bounds__(256, 3)
void moe_gemm(const float* __restrict__ W, float* __restrict__ outp) {
    constexpr int LDB = FC2 ? HH : FF;
    constexpr int KIT = KTOT / BK;

    int e  = blockIdx.x >> 5;
    int mt = blockIdx.x & 31;
    int off0 = g_off[e];
    int cnt  = g_off[e + 1] - off0;
    if (mt * BM >= cnt) return;
    int base = off0 + mt * BM;
    int n0   = blockIdx.y * BN;
    const float* Be = W + (size_t)e * KTOT * LDB;
    const __half* Abase = (FC2 ? g_mid : g_xg) + (size_t)base * KTOT;

    extern __shared__ char smem_raw[];
    uint32_t s_u32 = smem_u32(smem_raw);
    uint32_t s0    = (s_u32 + 127u) & ~127u;
    char*    s_gen = smem_raw + (s0 - s_u32);
    uint32_t sB0_u32 = s0 + ASTAGES * A_STAGE_BYTES;
    char*    sB0_gen = s_gen + ASTAGES * A_STAGE_BYTES;

    int tid = threadIdx.x, lane = tid & 31, wid = tid >> 5;
    int g = lane >> 2, t = lane & 3;
    int wm = wid >> 1, wn = wid & 1;
    int r0  = wm * 32;
    int nb0 = wn * 32;

    // A loader: row am = tid>>1, chunks aj + {0,1}
    int am = tid >> 1;
    int aj = (tid & 1) * 2;
    const __half* Arow = Abase + (size_t)am * KTOT;
    uint32_t a_dst_base = s0 + (uint32_t)am * 64u;
    uint32_t a_sw = (uint32_t)((am >> 1) & 3);
    // B loader: pair-row pr = tid>>4 (k rows 2pr, 2pr+1), chunk bc (4 n each)
    int pr = tid >> 4;
    int bc = tid & 15;
    const float* Bp0 = Be + (size_t)(2 * pr) * LDB + n0 + 4 * bc;
    uint32_t b_sts = (uint32_t)pr * 256u +
                     (uint32_t)((bc ^ ((pr & 3) << 1)) << 4);

    float acc[2][4][4];
#pragma unroll
    for (int mi = 0; mi < 2; mi++)
#pragma unroll
        for (int ni = 0; ni < 4; ni++)
#pragma unroll
            for (int c = 0; c < 4; c++) acc[mi][ni][c] = 0.f;

    uint32_t breg[4];

    auto issue_A = [&](int it) {
        uint32_t sb = (uint32_t)((it & (ASTAGES - 1)) * A_STAGE_BYTES);
        const __half* as = Arow + it * BK + aj * 8;
#pragma unroll
        for (int c = 0; c < 2; c++) {
            uint32_t ch = (uint32_t)(aj + c);
            cp_async16(a_dst_base + sb + ((ch ^ a_sw) << 4), as + c * 8);
        }
    };
    auto ldg_B = [&](int it) {
        const float* p0 = Bp0 + (size_t)(it * BK) * LDB;
        const float* p1 = p0 + LDB;
        float4 ev = *reinterpret_cast<const float4*>(p0);
        float4 ov = *reinterpret_cast<const float4*>(p1);
        breg[0] = pack_f16x2(ov.x, ev.x);
        breg[1] = pack_f16x2(ov.y, ev.y);
        breg[2] = pack_f16x2(ov.z, ev.z);
        breg[3] = pack_f16x2(ov.w, ev.w);
    };
    auto sts_B = [&](int it) {
        uint32_t sb = sB0_u32 + (uint32_t)((it & 1) * B_STAGE_BYTES);
        asm volatile("st.shared.v4.b32 [%0], {%1,%2,%3,%4};" :: "r"(sb + b_sts),
                     "r"(breg[0]), "r"(breg[1]), "r"(breg[2]), "r"(breg[3]));
    };

    // prologue: A stages 0..2 via cp.async; B stage 0 STS'd, B stage 1 in regs
    issue_A(0); cp_commit();
    issue_A(1); cp_commit();
    issue_A(2); cp_commit();
    ldg_B(0);
    sts_B(0);
    ldg_B(1);

    for (int it = 0; it < KIT; it++) {
        cp_wait<ASTAGES - 2>();
        __syncthreads();
        if (it + 1 < KIT) sts_B(it + 1);
        if (it + 2 < KIT) ldg_B(it + 2);
        if (it + 3 < KIT) issue_A(it + 3);
        cp_commit();

        char* sA = s_gen + (it & (ASTAGES - 1)) * A_STAGE_BYTES;
        char* sB = sB0_gen + (it & 1) * B_STAGE_BYTES;

#pragma unroll
        for (int ks = 0; ks < 2; ks++) {          // two k16 steps per BK=32
            // ---- A fragments: native half2 LDS.32 ----
            uint32_t a[2][4];
#pragma unroll
            for (int mi = 0; mi < 2; mi++) {
                int RA = r0 + mi * 16 + g;
                int RB = RA + 8;
                uint32_t c0 = (uint32_t)(ks * 2);
                uint32_t c1 = c0 + 1;
                uint32_t oA0 = (uint32_t)RA * 64u + ((c0 ^ (uint32_t)((RA >> 1) & 3)) << 4) + 4u * t;
                uint32_t oA1 = (uint32_t)RA * 64u + ((c1 ^ (uint32_t)((RA >> 1) & 3)) << 4) + 4u * t;
                uint32_t oB0 = (uint32_t)RB * 64u + ((c0 ^ (uint32_t)((RB >> 1) & 3)) << 4) + 4u * t;
                uint32_t oB1 = (uint32_t)RB * 64u + ((c1 ^ (uint32_t)((RB >> 1) & 3)) << 4) + 4u * t;
                a[mi][0] = *(const uint32_t*)(sA + oA0);
                a[mi][1] = *(const uint32_t*)(sA + oB0);
                a[mi][2] = *(const uint32_t*)(sA + oA1);
                a[mi][3] = *(const uint32_t*)(sA + oB1);
            }
            // ---- B fragments: one LDS.32 per reg (pre-packed half2) ----
            // rows rp = ks*8 + t and rp+4; swizzle chunk ^ ((rp&3)<<1):
            // 4 t-rows hit 4 disjoint chunk pairs -> all 32 banks distinct.
            uint32_t b[4][2];
            int rp  = ks * 8 + t;
            int rp4 = rp + 4;
            char* rowp  = sB + rp * 256;
            char* rowp4 = sB + rp4 * 256;
            uint32_t swz = (uint32_t)((rp & 3) << 1);   // same for rp4
#pragma unroll
            for (int ni = 0; ni < 4; ni++) {
                int n = nb0 + ni * 8 + g;
                uint32_t c = (uint32_t)(n >> 2);
                uint32_t w = (uint32_t)(n & 3) * 4u;
                b[ni][0] = *(const uint32_t*)(rowp  + ((c ^ swz) << 4) + w);
                b[ni][1] = *(const uint32_t*)(rowp4 + ((c ^ swz) << 4) + w);
            }
#pragma unroll
            for (int mi = 0; mi < 2; mi++)
#pragma unroll
                for (int ni = 0; ni < 4; ni++) {
                    asm volatile(
                        "mma.sync.aligned.m16n8k16.row.col.f32.f16.f16.f32 "
                        "{%0,%1,%2,%3}, {%4,%5,%6,%7}, {%8,%9}, {%0,%1,%2,%3};\n"
                        : "+f"(acc[mi][ni][0]), "+f"(acc[mi][ni][1]),
                          "+f"(acc[mi][ni][2]), "+f"(acc[mi][ni][3])
                        : "r"(a[mi][0]), "r"(a[mi][1]), "r"(a[mi][2]), "r"(a[mi][3]),
                          "r"(b[ni][0]), "r"(b[ni][1]));
                }
        }
    }

    // ---------------- epilogue ----------------
#pragma unroll
    for (int mi = 0; mi < 2; mi++) {
#pragma unroll
        for (int half = 0; half < 2; half++) {
            int row = r0 + mi * 16 + half * 8 + g;
            if (mt * BM + row >= cnt) continue;
            if (!FC2) {
                __half* op = g_mid + (size_t)(base + row) * FF + n0;
#pragma unroll
                for (int ni = 0; ni < 4; ni++) {
                    __half2 hv = __floats2half2_rn(
                        gelu_exact(acc[mi][ni][half * 2 + 0]),
                        gelu_exact(acc[mi][ni][half * 2 + 1]));
                    *reinterpret_cast<__half2*>(op + nb0 + ni * 8 + 2 * t) = hv;
                }
            } else {
                int token = g_perm[base + row];
                float p = g_maxprob[token];
                float* op = outp + (size_t)token * HH + n0;
#pragma unroll
                for (int ni = 0; ni < 4; ni++) {
                    float2 v;
                    v.x = acc[mi][ni][half * 2 + 0] * p;
                    v.y = acc[mi][ni][half * 2 + 1] * p;
                    *reinterpret_cast<float2*>(op + nb0 + ni * 8 + 2 * t) = v;
                }
            }
        }
    }
}

// ---------------- launch ----------------------------------------------------
extern "C" void kernel_launch(void* const* d_in, const int* in_sizes, int n_in,
                              void* d_out, int out_size) {
    const float* x  = (const float*)d_in[0];
    const float* Wr = (const float*)d_in[1];
    const float* br = (const float*)d_in[2];
    const float* W1 = (const float*)d_in[3];
    const float* W2 = (const float*)d_in[4];
    float* out = (float*)d_out;

    cudaFuncSetAttribute(moe_gemm<HH, false>,
                         cudaFuncAttributeMaxDynamicSharedMemorySize, SMEM_BYTES);
    cudaFuncSetAttribute(moe_gemm<FF, true>,
                         cudaFuncAttributeMaxDynamicSharedMemorySize, SMEM_BYTES);

    router_kernel<<<TT / 8, 256>>>(x, Wr, br);
    scan_kernel<<<1, 32>>>();
    permgather_kernel<<<TT, 256>>>(x);
    moe_gemm<HH, false><<<dim3(TILES_M * NE, FF / BN), 256, SMEM_BYTES>>>(W1, nullptr);
    moe_gemm<FF, true ><<<dim3(TILES_M * NE, HH / BN), 256, SMEM_BYTES>>>(W2, out);
}

// round 12
// speedup vs baseline: 1.1628x; 1.1628x over previous
#include <cuda_runtime.h>
#include <cuda_fp16.h>
#include <cstdint>

#define TT 4096   // tokens = B*S
#define HH 1024   // hidden
#define FF 4096   // ffn
#define NE 8      // experts

#define BM 128
#define BN 128
#define BK 32
#define ASTAGES 4                   // A: cp.async pipeline depth
#define TILES_ME 8                  // m-tiles per expert (1024-token cap = 24 sigma)
#define A_STAGE_BYTES 8192          // 128 x 32 fp16
#define B_STAGE_BYTES 8192          // 16 pair-rows x 128 half2
#define SMEM_BYTES (ASTAGES * A_STAGE_BYTES + 2 * B_STAGE_BYTES + 256)

// ---------------- scratch (static device globals; no runtime alloc) --------
__device__ __half g_xg [(size_t)(TT + BM) * HH];  // gathered acts, fp16
__device__ __half g_mid[(size_t)(TT + BM) * FF];  // fc1 out (perm order), fp16
__device__ int    g_perm[TT];
__device__ int    g_expert_of[TT];
__device__ float  g_maxprob[TT];
__device__ int    g_cnt[NE];        // zero at load; scan re-zeroes each run
__device__ int    g_off[NE + 1];
__device__ int    g_cur[NE];
__device__ int    g_done;           // router block completion counter

// ---------------- helpers ---------------------------------------------------
__device__ __forceinline__ uint32_t smem_u32(const void* p) {
    uint32_t a;
    asm("{ .reg .u64 t; cvta.to.shared.u64 t, %1; cvt.u32.u64 %0, t; }" : "=r"(a) : "l"(p));
    return a;
}
// pack two f32 -> f16x2 (first src -> HIGH half, second -> LOW half)
__device__ __forceinline__ uint32_t pack_f16x2(float hi, float lo) {
    uint32_t d;
    asm("cvt.rn.f16x2.f32 %0, %1, %2;" : "=r"(d) : "f"(hi), "f"(lo));
    return d;
}
__device__ __forceinline__ float gelu_exact(float v) {
    return 0.5f * v * (1.0f + erff(v * 0.7071067811865476f));
}
__device__ __forceinline__ void cp_async16(uint32_t dst, const void* src) {
    asm volatile("cp.async.cg.shared.global [%0], [%1], 16;" :: "r"(dst), "l"(src));
}
__device__ __forceinline__ void cp_commit() {
    asm volatile("cp.async.commit_group;" ::: "memory");
}
template<int N>
__device__ __forceinline__ void cp_wait() {
    asm volatile("cp.async.wait_group %0;" :: "n"(N) : "memory");
}

// ---------------- routing: router with fused scan ---------------------------
__global__ void router_kernel(const float* __restrict__ x,
                              const float* __restrict__ Wr,
                              const float* __restrict__ br) {
    int warp = (blockIdx.x * blockDim.x + threadIdx.x) >> 5;
    int lane = threadIdx.x & 31;
    const float* xr = x + (size_t)warp * HH;
    float acc[NE];
#pragma unroll
    for (int e = 0; e < NE; e++) acc[e] = 0.f;
    for (int i = lane; i < HH; i += 32) {
        float xv = xr[i];
        const float4* w4 = reinterpret_cast<const float4*>(Wr + i * NE);
        float4 w0 = w4[0], w1 = w4[1];
        acc[0] += xv * w0.x; acc[1] += xv * w0.y;
        acc[2] += xv * w0.z; acc[3] += xv * w0.w;
        acc[4] += xv * w1.x; acc[5] += xv * w1.y;
        acc[6] += xv * w1.z; acc[7] += xv * w1.w;
    }
#pragma unroll
    for (int e = 0; e < NE; e++) {
#pragma unroll
        for (int o = 16; o > 0; o >>= 1)
            acc[e] += __shfl_xor_sync(0xffffffffu, acc[e], o);
    }
    if (lane == 0) {
        float best = acc[0] + br[0]; int bi = 0;
#pragma unroll
        for (int e = 1; e < NE; e++) {
            float v = acc[e] + br[e];
            if (v > best) { best = v; bi = e; }
        }
        g_expert_of[warp] = bi;
        g_maxprob[warp]   = 1.0f / (1.0f + expf(-best));
        atomicAdd(&g_cnt[bi], 1);
    }
    // fused scan: last block to finish computes offsets + resets counters
    __syncthreads();
    if (threadIdx.x == 0) {
        __threadfence();
        int d = atomicAdd(&g_done, 1);
        if (d == (int)gridDim.x - 1) {
            int off = 0;
            for (int e = 0; e < NE; e++) {
                g_off[e] = off; g_cur[e] = off; off += g_cnt[e];
                g_cnt[e] = 0;                    // ready for next replay
            }
            g_off[NE] = off;
            g_done = 0;                          // ready for next replay
            __threadfence();
        }
    }
}

// fused: compute perm slot for this token AND gather its row to fp16
__global__ void permgather_kernel(const float* __restrict__ x) {
    __shared__ int s_slot;
    int tok = blockIdx.x;
    if (threadIdx.x == 0) {
        int e = g_expert_of[tok];
        int slot = atomicAdd(&g_cur[e], 1);
        g_perm[slot] = tok;
        s_slot = slot;
    }
    __syncthreads();
    int slot = s_slot;
    const float4* src = reinterpret_cast<const float4*>(x + (size_t)tok * HH);
    int c = threadIdx.x;            // 256 threads, 4 elems each
    float4 v = src[c];
    __half2 h0 = __floats2half2_rn(v.x, v.y);
    __half2 h1 = __floats2half2_rn(v.z, v.w);
    uint2 pk;
    pk.x = *reinterpret_cast<uint32_t*>(&h0);
    pk.y = *reinterpret_cast<uint32_t*>(&h1);
    *reinterpret_cast<uint2*>(g_xg + (size_t)slot * HH + 4 * c) = pk;
}

// ---------------- pipelined fp16 grouped GEMM (BK=32, best config) ----------
// FC1: g_mid = fp16( gelu( g_xg @ W1[e] ) )   K=HH, N over FF
// FC2: out   = ( g_mid @ W2[e] ) * p          K=FF, N over HH
//
// 256 threads, 8 warps (4 m x 2 n), warp tile 32x64, mma m16n8k16 f16.f16.f32.
// At the legacy-HMMA issue-rate ceiling (~190 TF/s); grid trimmed to
// TILES_ME=8 m-tiles/expert to cut empty-block scheduling waves.
template<int KTOT, bool FC2>
__global__ __launch_bounds__(256, 2)
void moe_gemm(const float* __restrict__ W, float* __restrict__ outp) {
    constexpr int LDB = FC2 ? HH : FF;
    constexpr int KIT = KTOT / BK;

    int e  = blockIdx.x >> 3;           // / TILES_ME
    int mt = blockIdx.x & 7;
    int off0 = g_off[e];
    int cnt  = g_off[e + 1] - off0;
    if (mt * BM >= cnt) return;
    int base = off0 + mt * BM;
    int n0   = blockIdx.y * BN;
    const float* Be = W + (size_t)e * KTOT * LDB;
    const __half* Abase = (FC2 ? g_mid : g_xg) + (size_t)base * KTOT;

    extern __shared__ char smem_raw[];
    uint32_t s_u32 = smem_u32(smem_raw);
    uint32_t s0    = (s_u32 + 127u) & ~127u;
    char*    s_gen = smem_raw + (s0 - s_u32);
    uint32_t sB0_u32 = s0 + ASTAGES * A_STAGE_BYTES;
    char*    sB0_gen = s_gen + ASTAGES * A_STAGE_BYTES;

    int tid = threadIdx.x, lane = tid & 31, wid = tid >> 5;
    int g = lane >> 2, t = lane & 3;
    int wm = wid >> 1, wn = wid & 1;
    int r0  = wm * 32;
    int nb0 = wn * 64;

    // A loader: row am = tid>>1, chunks aj + {0,1}
    int am = tid >> 1;
    int aj = (tid & 1) * 2;
    const __half* Arow = Abase + (size_t)am * KTOT;
    uint32_t a_dst_base = s0 + (uint32_t)am * 64u;
    uint32_t a_sw = (uint32_t)((am >> 1) & 3);
    // B loader: pair-row pr = tid>>4 (k rows 2pr, 2pr+1), n block j
    int pr = tid >> 4;
    int bj = tid & 15;
    const float* Bp0 = Be + (size_t)(2 * pr) * LDB + n0 + 8 * bj;
    uint32_t b_sts0 = (uint32_t)pr * 512u + (uint32_t)(((2 * bj) ^ ((pr & 7) << 1)) << 4);
    uint32_t b_sts1 = (uint32_t)pr * 512u + (uint32_t)(((2 * bj + 1) ^ ((pr & 7) << 1)) << 4);

    float acc[2][8][4];
#pragma unroll
    for (int mi = 0; mi < 2; mi++)
#pragma unroll
        for (int ni = 0; ni < 8; ni++)
#pragma unroll
            for (int c = 0; c < 4; c++) acc[mi][ni][c] = 0.f;

    uint32_t breg[8];

    auto issue_A = [&](int it) {
        uint32_t sb = (uint32_t)((it & (ASTAGES - 1)) * A_STAGE_BYTES);
        const __half* as = Arow + it * BK + aj * 8;
#pragma unroll
        for (int c = 0; c < 2; c++) {
            uint32_t ch = (uint32_t)(aj + c);
            cp_async16(a_dst_base + sb + ((ch ^ a_sw) << 4), as + c * 8);
        }
    };
    auto ldg_B = [&](int it) {
        const float* p0 = Bp0 + (size_t)(it * BK) * LDB;
        const float* p1 = p0 + LDB;
        float4 e0 = *reinterpret_cast<const float4*>(p0);
        float4 e1 = *reinterpret_cast<const float4*>(p0 + 4);
        float4 o0 = *reinterpret_cast<const float4*>(p1);
        float4 o1 = *reinterpret_cast<const float4*>(p1 + 4);
        breg[0] = pack_f16x2(o0.x, e0.x);
        breg[1] = pack_f16x2(o0.y, e0.y);
        breg[2] = pack_f16x2(o0.z, e0.z);
        breg[3] = pack_f16x2(o0.w, e0.w);
        breg[4] = pack_f16x2(o1.x, e1.x);
        breg[5] = pack_f16x2(o1.y, e1.y);
        breg[6] = pack_f16x2(o1.z, e1.z);
        breg[7] = pack_f16x2(o1.w, e1.w);
    };
    auto sts_B = [&](int it) {
        uint32_t sb = sB0_u32 + (uint32_t)((it & 1) * B_STAGE_BYTES);
        asm volatile("st.shared.v4.b32 [%0], {%1,%2,%3,%4};" :: "r"(sb + b_sts0),
                     "r"(breg[0]), "r"(breg[1]), "r"(breg[2]), "r"(breg[3]));
        asm volatile("st.shared.v4.b32 [%0], {%1,%2,%3,%4};" :: "r"(sb + b_sts1),
                     "r"(breg[4]), "r"(breg[5]), "r"(breg[6]), "r"(breg[7]));
    };

    // prologue: A stages 0..2 via cp.async; B stage 0 STS'd, B stage 1 in regs
    issue_A(0); cp_commit();
    issue_A(1); cp_commit();
    issue_A(2); cp_commit();
    ldg_B(0);
    sts_B(0);
    ldg_B(1);

    for (int it = 0; it < KIT; it++) {
        cp_wait<ASTAGES - 2>();
        __syncthreads();
        if (it + 1 < KIT) sts_B(it + 1);
        if (it + 2 < KIT) ldg_B(it + 2);
        if (it + 3 < KIT) issue_A(it + 3);
        cp_commit();

        char* sA = s_gen + (it & (ASTAGES - 1)) * A_STAGE_BYTES;
        char* sB = sB0_gen + (it & 1) * B_STAGE_BYTES;

#pragma unroll
        for (int ks = 0; ks < 2; ks++) {          // two k16 steps per BK=32
            // ---- A fragments: native half2 LDS.32 ----
            uint32_t a[2][4];
#pragma unroll
            for (int mi = 0; mi < 2; mi++) {
                int RA = r0 + mi * 16 + g;
                int RB = RA + 8;
                uint32_t c0 = (uint32_t)(ks * 2);
                uint32_t c1 = c0 + 1;
                uint32_t oA0 = (uint32_t)RA * 64u + ((c0 ^ (uint32_t)((RA >> 1) & 3)) << 4) + 4u * t;
                uint32_t oA1 = (uint32_t)RA * 64u + ((c1 ^ (uint32_t)((RA >> 1) & 3)) << 4) + 4u * t;
                uint32_t oB0 = (uint32_t)RB * 64u + ((c0 ^ (uint32_t)((RB >> 1) & 3)) << 4) + 4u * t;
                uint32_t oB1 = (uint32_t)RB * 64u + ((c1 ^ (uint32_t)((RB >> 1) & 3)) << 4) + 4u * t;
                a[mi][0] = *(const uint32_t*)(sA + oA0);
                a[mi][1] = *(const uint32_t*)(sA + oB0);
                a[mi][2] = *(const uint32_t*)(sA + oA1);
                a[mi][3] = *(const uint32_t*)(sA + oB1);
            }
            // ---- B fragments: one LDS.32 per reg (pre-packed half2) ----
            uint32_t b[8][2];
            int rp  = ks * 8 + t;
            int rp4 = rp + 4;
            char* rowp  = sB + rp * 512;
            char* rowp4 = sB + rp4 * 512;
            uint32_t swz  = (uint32_t)((rp & 7) << 1);
            uint32_t swz4 = (uint32_t)((rp4 & 7) << 1);
#pragma unroll
            for (int ni = 0; ni < 8; ni++) {
                int n = nb0 + ni * 8 + g;
                uint32_t c = (uint32_t)(n >> 2);
                uint32_t w = (uint32_t)(n & 3) * 4u;
                b[ni][0] = *(const uint32_t*)(rowp  + ((c ^ swz)  << 4) + w);
                b[ni][1] = *(const uint32_t*)(rowp4 + ((c ^ swz4) << 4) + w);
            }
#pragma unroll
            for (int mi = 0; mi < 2; mi++)
#pragma unroll
                for (int ni = 0; ni < 8; ni++) {
                    asm volatile(
                        "mma.sync.aligned.m16n8k16.row.col.f32.f16.f16.f32 "
                        "{%0,%1,%2,%3}, {%4,%5,%6,%7}, {%8,%9}, {%0,%1,%2,%3};\n"
                        : "+f"(acc[mi][ni][0]), "+f"(acc[mi][ni][1]),
                          "+f"(acc[mi][ni][2]), "+f"(acc[mi][ni][3])
                        : "r"(a[mi][0]), "r"(a[mi][1]), "r"(a[mi][2]), "r"(a[mi][3]),
                          "r"(b[ni][0]), "r"(b[ni][1]));
                }
        }
    }

    // ---------------- epilogue ----------------
#pragma unroll
    for (int mi = 0; mi < 2; mi++) {
#pragma unroll
        for (int half = 0; half < 2; half++) {
            int row = r0 + mi * 16 + half * 8 + g;
            if (mt * BM + row >= cnt) continue;
            if (!FC2) {
                __half* op = g_mid + (size_t)(base + row) * FF + n0;
#pragma unroll
                for (int ni = 0; ni < 8; ni++) {
                    __half2 hv = __floats2half2_rn(
                        gelu_exact(acc[mi][ni][half * 2 + 0]),
                        gelu_exact(acc[mi][ni][half * 2 + 1]));
                    *reinterpret_cast<__half2*>(op + nb0 + ni * 8 + 2 * t) = hv;
                }
            } else {
                int token = g_perm[base + row];
                float p = g_maxprob[token];
                float* op = outp + (size_t)token * HH + n0;
#pragma unroll
                for (int ni = 0; ni < 8; ni++) {
                    float2 v;
                    v.x = acc[mi][ni][half * 2 + 0] * p;
                    v.y = acc[mi][ni][half * 2 + 1] * p;
                    *reinterpret_cast<float2*>(op + nb0 + ni * 8 + 2 * t) = v;
                }
            }
        }
    }
}

// ---------------- launch ----------------------------------------------------
extern "C" void kernel_launch(void* const* d_in, const int* in_sizes, int n_in,
                              void* d_out, int out_size) {
    const float* x  = (const float*)d_in[0];
    const float* Wr = (const float*)d_in[1];
    const float* br = (const float*)d_in[2];
    const float* W1 = (const float*)d_in[3];
    const float* W2 = (const float*)d_in[4];
    float* out = (float*)d_out;

    cudaFuncSetAttribute(moe_gemm<HH, false>,
                         cudaFuncAttributeMaxDynamicSharedMemorySize, SMEM_BYTES);
    cudaFuncSetAttribute(moe_gemm<FF, true>,
                         cudaFuncAttributeMaxDynamicSharedMemorySize, SMEM_BYTES);

    router_kernel<<<TT / 8, 256>>>(x, Wr, br);          // scan fused (last block)
    permgather_kernel<<<TT, 256>>>(x);
    moe_gemm<HH, false><<<dim3(TILES_ME * NE, FF / BN), 256, SMEM_BYTES>>>(W1, nullptr);
    moe_gemm<FF, true ><<<dim3(TILES_ME * NE, HH / BN), 256, SMEM_BYTES>>>(W2, out);
}

// round 13
// speedup vs baseline: 1.2591x; 1.0828x over previous
#include <cuda_runtime.h>
#include <cuda_fp16.h>
#include <cstdint>

#define TT 4096   // tokens = B*S
#define HH 1024   // hidden
#define FF 4096   // ffn
#define NE 8      // experts

#define BM 128
#define BN 128
#define BK 32
#define ASTAGES 4                   // A: cp.async pipeline depth
#define TILES_ME 8                  // m-tiles per expert (1024-token cap = 24 sigma)
#define A_STAGE_BYTES 8192          // 128 x 32 fp16
#define B_STAGE_BYTES 8192          // 8 quad-rows x 128 n x 8B
#define SMEM_BYTES (ASTAGES * A_STAGE_BYTES + 2 * B_STAGE_BYTES + 256)

// ---------------- scratch (static device globals; no runtime alloc) --------
__device__ __half g_xg [(size_t)(TT + BM) * HH];  // gathered acts, fp16
__device__ __half g_mid[(size_t)(TT + BM) * FF];  // fc1 out (perm order), fp16
__device__ int    g_perm[TT];
__device__ int    g_expert_of[TT];
__device__ float  g_maxprob[TT];
__device__ int    g_cnt[NE];        // zero at load; router re-zeroes each run
__device__ int    g_off[NE + 1];
__device__ int    g_cur[NE];
__device__ int    g_done;           // router block completion counter

// ---------------- helpers ---------------------------------------------------
__device__ __forceinline__ uint32_t smem_u32(const void* p) {
    uint32_t a;
    asm("{ .reg .u64 t; cvta.to.shared.u64 t, %1; cvt.u32.u64 %0, t; }" : "=r"(a) : "l"(p));
    return a;
}
// pack two f32 -> f16x2 (first src -> HIGH half, second -> LOW half)
__device__ __forceinline__ uint32_t pack_f16x2(float hi, float lo) {
    uint32_t d;
    asm("cvt.rn.f16x2.f32 %0, %1, %2;" : "=r"(d) : "f"(hi), "f"(lo));
    return d;
}
__device__ __forceinline__ float gelu_exact(float v) {
    return 0.5f * v * (1.0f + erff(v * 0.7071067811865476f));
}
__device__ __forceinline__ void cp_async16(uint32_t dst, const void* src) {
    asm volatile("cp.async.cg.shared.global [%0], [%1], 16;" :: "r"(dst), "l"(src));
}
__device__ __forceinline__ void cp_commit() {
    asm volatile("cp.async.commit_group;" ::: "memory");
}
template<int N>
__device__ __forceinline__ void cp_wait() {
    asm volatile("cp.async.wait_group %0;" :: "n"(N) : "memory");
}

// ---------------- routing: router with fused scan ---------------------------
__global__ void router_kernel(const float* __restrict__ x,
                              const float* __restrict__ Wr,
                              const float* __restrict__ br) {
    int warp = (blockIdx.x * blockDim.x + threadIdx.x) >> 5;
    int lane = threadIdx.x & 31;
    const float* xr = x + (size_t)warp * HH;
    float acc[NE];
#pragma unroll
    for (int e = 0; e < NE; e++) acc[e] = 0.f;
    for (int i = lane; i < HH; i += 32) {
        float xv = xr[i];
        const float4* w4 = reinterpret_cast<const float4*>(Wr + i * NE);
        float4 w0 = w4[0], w1 = w4[1];
        acc[0] += xv * w0.x; acc[1] += xv * w0.y;
        acc[2] += xv * w0.z; acc[3] += xv * w0.w;
        acc[4] += xv * w1.x; acc[5] += xv * w1.y;
        acc[6] += xv * w1.z; acc[7] += xv * w1.w;
    }
#pragma unroll
    for (int e = 0; e < NE; e++) {
#pragma unroll
        for (int o = 16; o > 0; o >>= 1)
            acc[e] += __shfl_xor_sync(0xffffffffu, acc[e], o);
    }
    if (lane == 0) {
        float best = acc[0] + br[0]; int bi = 0;
#pragma unroll
        for (int e = 1; e < NE; e++) {
            float v = acc[e] + br[e];
            if (v > best) { best = v; bi = e; }
        }
        g_expert_of[warp] = bi;
        g_maxprob[warp]   = 1.0f / (1.0f + expf(-best));
        atomicAdd(&g_cnt[bi], 1);
    }
    // fused scan: last block to finish computes offsets + resets counters
    __syncthreads();
    if (threadIdx.x == 0) {
        __threadfence();
        int d = atomicAdd(&g_done, 1);
        if (d == (int)gridDim.x - 1) {
            int off = 0;
            for (int e = 0; e < NE; e++) {
                g_off[e] = off; g_cur[e] = off; off += g_cnt[e];
                g_cnt[e] = 0;                    // ready for next replay
            }
            g_off[NE] = off;
            g_done = 0;                          // ready for next replay
            __threadfence();
        }
    }
}

// fused: compute perm slot for this token AND gather its row to fp16
__global__ void permgather_kernel(const float* __restrict__ x) {
    __shared__ int s_slot;
    int tok = blockIdx.x;
    if (threadIdx.x == 0) {
        int e = g_expert_of[tok];
        int slot = atomicAdd(&g_cur[e], 1);
        g_perm[slot] = tok;
        s_slot = slot;
    }
    __syncthreads();
    int slot = s_slot;
    const float4* src = reinterpret_cast<const float4*>(x + (size_t)tok * HH);
    int c = threadIdx.x;            // 256 threads, 4 elems each
    float4 v = src[c];
    __half2 h0 = __floats2half2_rn(v.x, v.y);
    __half2 h1 = __floats2half2_rn(v.z, v.w);
    uint2 pk;
    pk.x = *reinterpret_cast<uint32_t*>(&h0);
    pk.y = *reinterpret_cast<uint32_t*>(&h1);
    *reinterpret_cast<uint2*>(g_xg + (size_t)slot * HH + 4 * c) = pk;
}

// ---------------- pipelined fp16 grouped GEMM (LDSM + quad-pack B) ----------
// FC1: g_mid = fp16( gelu( g_xg @ W1[e] ) )   K=HH, N over FF
// FC2: out   = ( g_mid @ W2[e] ) * p          K=FF, N over HH
//
// 256 threads, 8 warps (4 m x 2 n), warp tile 32x64, mma m16n8k16 f16.f16.f32.
// Per-thread-iter shared loads: 4 LDSM.x4 (A) + 16 LDS.64 (B)  [was 48 LDS.32]
// Smem A: fp16 [128][32], 64B rows, chunk16 ^ ((m>>1)&3), 4-stage cp.async.
// Smem B: quad-packed [8 qr][128 n] 8B elems {h2(k,k+1), h2(k+8,k+9)},
//         element col n ^ (4*qr) swizzle, double-buffered LDG->cvt->STS.
template<int KTOT, bool FC2>
__global__ __launch_bounds__(256, 2)
void moe_gemm(const float* __restrict__ W, float* __restrict__ outp) {
    constexpr int LDB = FC2 ? HH : FF;
    constexpr int KIT = KTOT / BK;

    int e  = blockIdx.x >> 3;           // / TILES_ME
    int mt = blockIdx.x & 7;
    int off0 = g_off[e];
    int cnt  = g_off[e + 1] - off0;
    if (mt * BM >= cnt) return;
    int base = off0 + mt * BM;
    int n0   = blockIdx.y * BN;
    const float* Be = W + (size_t)e * KTOT * LDB;
    const __half* Abase = (FC2 ? g_mid : g_xg) + (size_t)base * KTOT;

    extern __shared__ char smem_raw[];
    uint32_t s_u32 = smem_u32(smem_raw);
    uint32_t s0    = (s_u32 + 127u) & ~127u;
    uint32_t sB0_u32 = s0 + ASTAGES * A_STAGE_BYTES;

    int tid = threadIdx.x, lane = tid & 31, wid = tid >> 5;
    int g = lane >> 2, t = lane & 3;
    int wm = wid >> 1, wn = wid & 1;
    int r0  = wm * 32;
    int nb0 = wn * 64;

    // ---- A ldmatrix per-lane constants ----
    // lane l -> matrix q = l>>3; rows 0-7 vs 8-15 via q&1; chunk +1 via q>>1
    int i8  = lane & 7;
    int qlo = (lane >> 3) & 1;
    int qhi = lane >> 4;
    uint32_t aoff = (uint32_t)(r0 + qlo * 8 + i8) * 64u;     // + mi*1024
    uint32_t s_a  = (uint32_t)((i8 >> 1) & 3);
    uint32_t Ta0  = ((uint32_t)qhi ^ s_a) << 4;              // ks=0 chunk
    uint32_t Ta1  = ((uint32_t)(2 + qhi) ^ s_a) << 4;        // ks=1 chunk

    // A loader: row am = tid>>1, chunks aj + {0,1}
    int am = tid >> 1;
    int aj = (tid & 1) * 2;
    const __half* Arow = Abase + (size_t)am * KTOT;
    uint32_t a_dst_base = s0 + (uint32_t)am * 64u;
    uint32_t a_sw = (uint32_t)((am >> 1) & 3);

    // B loader: warp w handles quad-row qr=w (k rows rB, rB+1, rB+8, rB+9),
    // lane nb covers 4 n columns.
    int qrl = wid;
    int nb  = lane;
    int rB  = 16 * (qrl >> 2) + 2 * (qrl & 3);
    const float* Bq = Be + (size_t)rB * LDB + n0 + 4 * nb;
    uint32_t b_sts_base = (uint32_t)(qrl * 1024 + ((nb ^ qrl) * 32));

    float acc[2][8][4];
#pragma unroll
    for (int mi = 0; mi < 2; mi++)
#pragma unroll
        for (int ni = 0; ni < 8; ni++)
#pragma unroll
            for (int c = 0; c < 4; c++) acc[mi][ni][c] = 0.f;

    uint32_t breg[8];

    auto issue_A = [&](int it) {
        uint32_t sb = (uint32_t)((it & (ASTAGES - 1)) * A_STAGE_BYTES);
        const __half* as = Arow + it * BK + aj * 8;
#pragma unroll
        for (int c = 0; c < 2; c++) {
            uint32_t ch = (uint32_t)(aj + c);
            cp_async16(a_dst_base + sb + ((ch ^ a_sw) << 4), as + c * 8);
        }
    };
    auto ldg_B = [&](int it) {
        const float* p = Bq + (size_t)(it * BK) * LDB;
        float4 r0v = *reinterpret_cast<const float4*>(p);
        float4 r1v = *reinterpret_cast<const float4*>(p + LDB);
        float4 r8v = *reinterpret_cast<const float4*>(p + 8 * (size_t)LDB);
        float4 r9v = *reinterpret_cast<const float4*>(p + 9 * (size_t)LDB);
        breg[0] = pack_f16x2(r1v.x, r0v.x);   // elem j=0: low h2 (k,k+1)
        breg[1] = pack_f16x2(r9v.x, r8v.x);   //          high h2 (k+8,k+9)
        breg[2] = pack_f16x2(r1v.y, r0v.y);
        breg[3] = pack_f16x2(r9v.y, r8v.y);
        breg[4] = pack_f16x2(r1v.z, r0v.z);
        breg[5] = pack_f16x2(r9v.z, r8v.z);
        breg[6] = pack_f16x2(r1v.w, r0v.w);
        breg[7] = pack_f16x2(r9v.w, r8v.w);
    };
    auto sts_B = [&](int it) {
        uint32_t sb = sB0_u32 + (uint32_t)((it & 1) * B_STAGE_BYTES) + b_sts_base;
        asm volatile("st.shared.v4.b32 [%0], {%1,%2,%3,%4};" :: "r"(sb),
                     "r"(breg[0]), "r"(breg[1]), "r"(breg[2]), "r"(breg[3]));
        asm volatile("st.shared.v4.b32 [%0], {%1,%2,%3,%4};" :: "r"(sb + 16),
                     "r"(breg[4]), "r"(breg[5]), "r"(breg[6]), "r"(breg[7]));
    };

    // prologue: A stages 0..2 via cp.async; B stage 0 STS'd, B stage 1 in regs
    issue_A(0); cp_commit();
    issue_A(1); cp_commit();
    issue_A(2); cp_commit();
    ldg_B(0);
    sts_B(0);
    ldg_B(1);

    for (int it = 0; it < KIT; it++) {
        cp_wait<ASTAGES - 2>();
        __syncthreads();
        if (it + 1 < KIT) sts_B(it + 1);
        if (it + 2 < KIT) ldg_B(it + 2);
        if (it + 3 < KIT) issue_A(it + 3);
        cp_commit();

        uint32_t sAu = s0 + (uint32_t)((it & (ASTAGES - 1)) * A_STAGE_BYTES);
        uint32_t sBu = sB0_u32 + (uint32_t)((it & 1) * B_STAGE_BYTES);

#pragma unroll
        for (int ks = 0; ks < 2; ks++) {          // two k16 steps per BK=32
            // ---- A fragments: one ldmatrix.x4 per (mi) ----
            uint32_t a[2][4];
            uint32_t Ta = ks ? Ta1 : Ta0;
#pragma unroll
            for (int mi = 0; mi < 2; mi++) {
                uint32_t addr = sAu + aoff + (uint32_t)(mi * 1024) + Ta;
                asm volatile(
                    "ldmatrix.sync.aligned.m8n8.x4.shared.b16 {%0,%1,%2,%3}, [%4];"
                    : "=r"(a[mi][0]), "=r"(a[mi][1]),
                      "=r"(a[mi][2]), "=r"(a[mi][3])
                    : "r"(addr));
            }
            // ---- B fragments: one LDS.64 per ni (quad-packed) ----
            uint32_t b[8][2];
            uint32_t qr   = (uint32_t)(ks * 4 + t);
            uint32_t rowb = sBu + qr * 1024u;
            uint32_t fq   = qr * 4u;
#pragma unroll
            for (int ni = 0; ni < 8; ni++) {
                uint32_t n = (uint32_t)(nb0 + ni * 8 + g);
                uint32_t addr = rowb + ((n ^ fq) << 3);
                asm volatile("ld.shared.v2.b32 {%0,%1}, [%2];"
                             : "=r"(b[ni][0]), "=r"(b[ni][1]) : "r"(addr));
            }
#pragma unroll
            for (int mi = 0; mi < 2; mi++)
#pragma unroll
                for (int ni = 0; ni < 8; ni++) {
                    asm volatile(
                        "mma.sync.aligned.m16n8k16.row.col.f32.f16.f16.f32 "
                        "{%0,%1,%2,%3}, {%4,%5,%6,%7}, {%8,%9}, {%0,%1,%2,%3};\n"
                        : "+f"(acc[mi][ni][0]), "+f"(acc[mi][ni][1]),
                          "+f"(acc[mi][ni][2]), "+f"(acc[mi][ni][3])
                        : "r"(a[mi][0]), "r"(a[mi][1]), "r"(a[mi][2]), "r"(a[mi][3]),
                          "r"(b[ni][0]), "r"(b[ni][1]));
                }
        }
    }

    // ---------------- epilogue ----------------
#pragma unroll
    for (int mi = 0; mi < 2; mi++) {
#pragma unroll
        for (int half = 0; half < 2; half++) {
            int row = r0 + mi * 16 + half * 8 + g;
            if (mt * BM + row >= cnt) continue;
            if (!FC2) {
                __half* op = g_mid + (size_t)(base + row) * FF + n0;
#pragma unroll
                for (int ni = 0; ni < 8; ni++) {
                    __half2 hv = __floats2half2_rn(
                        gelu_exact(acc[mi][ni][half * 2 + 0]),
                        gelu_exact(acc[mi][ni][half * 2 + 1]));
                    *reinterpret_cast<__half2*>(op + nb0 + ni * 8 + 2 * t) = hv;
                }
            } else {
                int token = g_perm[base + row];
                float p = g_maxprob[token];
                float* op = outp + (size_t)token * HH + n0;
#pragma unroll
                for (int ni = 0; ni < 8; ni++) {
                    float2 v;
                    v.x = acc[mi][ni][half * 2 + 0] * p;
                    v.y = acc[mi][ni][half * 2 + 1] * p;
                    *reinterpret_cast<float2*>(op + nb0 + ni * 8 + 2 * t) = v;
                }
            }
        }
    }
}

// ---------------- launch ----------------------------------------------------
extern "C" void kernel_launch(void* const* d_in, const int* in_sizes, int n_in,
                              void* d_out, int out_size) {
    const float* x  = (const float*)d_in[0];
    const float* Wr = (const float*)d_in[1];
    const float* br = (const float*)d_in[2];
    const float* W1 = (const float*)d_in[3];
    const float* W2 = (const float*)d_in[4];
    float* out = (float*)d_out;

    cudaFuncSetAttribute(moe_gemm<HH, false>,
                         cudaFuncAttributeMaxDynamicSharedMemorySize, SMEM_BYTES);
    cudaFuncSetAttribute(moe_gemm<FF, true>,
                         cudaFuncAttributeMaxDynamicSharedMemorySize, SMEM_BYTES);

    router_kernel<<<TT / 8, 256>>>(x, Wr, br);          // scan fused (last block)
    permgather_kernel<<<TT, 256>>>(x);
    moe_gemm<HH, false><<<dim3(TILES_ME * NE, FF / BN), 256, SMEM_BYTES>>>(W1, nullptr);
    moe_gemm<FF, true ><<<dim3(TILES_ME * NE, HH / BN), 256, SMEM_BYTES>>>(W2, out);
}